// round 9
// baseline (speedup 1.0000x reference)
#include <cuda_runtime.h>
#include <cuda_bf16.h>
#include <cuda_fp16.h>
typedef unsigned int u32; typedef unsigned long long u64;

#define NELEM (4*4096*64)
__device__ __nv_bfloat16 g_Khi[NELEM], g_Klo[NELEM];   // [b][n][c]
__device__ __nv_bfloat16 g_Qhi[NELEM], g_Qlo[NELEM];   // [b][m][c]
__device__ __half        g_Vh [NELEM];                  // [b][n][c]  fp16
__device__ float g_E[NELEM];                            // [b][c][n]

#define SWZ(row, chunk) (((u32)(row) << 7) + ((u32)(((chunk) ^ ((row) & 7))) << 4))

__device__ __forceinline__ u32 smem_u32(const void* p) {
    u32 a; asm("{ .reg .u64 t; cvta.to.shared.u64 t, %1; cvt.u32.u64 %0, t; }" : "=r"(a) : "l"(p)); return a;
}
__device__ __forceinline__ void cpa16(u32 dst, const void* src) {
    asm volatile("cp.async.cg.shared.global [%0], [%1], 16;" :: "r"(dst), "l"(src));
}
__device__ __forceinline__ void cpa_commit() { asm volatile("cp.async.commit_group;"); }
__device__ __forceinline__ void cpa_wait0()  { asm volatile("cp.async.wait_group 0;"); }
__device__ __forceinline__ void ldsm4(u32* r, u32 a) {
    asm volatile("ldmatrix.sync.aligned.m8n8.x4.shared.b16 {%0,%1,%2,%3},[%4];"
        : "=r"(r[0]), "=r"(r[1]), "=r"(r[2]), "=r"(r[3]) : "r"(a));
}
__device__ __forceinline__ void ldsm4t(u32* r, u32 a) {
    asm volatile("ldmatrix.sync.aligned.m8n8.x4.trans.shared.b16 {%0,%1,%2,%3},[%4];"
        : "=r"(r[0]), "=r"(r[1]), "=r"(r[2]), "=r"(r[3]) : "r"(a));
}
__device__ __forceinline__ void mma_bf16(float* d, const u32* a, u32 b0, u32 b1) {
    asm volatile("mma.sync.aligned.m16n8k16.row.col.f32.bf16.bf16.f32 "
        "{%0,%1,%2,%3},{%4,%5,%6,%7},{%8,%9},{%0,%1,%2,%3};"
        : "+f"(d[0]), "+f"(d[1]), "+f"(d[2]), "+f"(d[3])
        : "r"(a[0]), "r"(a[1]), "r"(a[2]), "r"(a[3]), "r"(b0), "r"(b1));
}
__device__ __forceinline__ void mma_f16(float* d, const u32* a, u32 b0, u32 b1) {
    asm volatile("mma.sync.aligned.m16n8k16.row.col.f32.f16.f16.f32 "
        "{%0,%1,%2,%3},{%4,%5,%6,%7},{%8,%9},{%0,%1,%2,%3};"
        : "+f"(d[0]), "+f"(d[1]), "+f"(d[2]), "+f"(d[3])
        : "r"(a[0]), "r"(a[1]), "r"(a[2]), "r"(a[3]), "r"(b0), "r"(b1));
}
__device__ __forceinline__ u32 pack_f16(float lo, float hi) {
    __half2 h = __floats2half2_rn(lo, hi);
    return *(u32*)&h;
}
__device__ __forceinline__ u64 pk2(float x, float y) {
    u64 r; asm("mov.b64 %0, {%1,%2};" : "=l"(r) : "f"(x), "f"(y)); return r;
}
__device__ __forceinline__ float2 upk2(u64 v) {
    float2 f; asm("mov.b64 {%0,%1}, %2;" : "=f"(f.x), "=f"(f.y) : "l"(v)); return f;
}
__device__ __forceinline__ void fma2(u64 &d, u64 a, u64 b) {
    asm("fma.rn.f32x2 %0, %1, %2, %0;" : "+l"(d) : "l"(a), "l"(b));
}

// ========== Kernel 1: MERGED projections (theta,phi,g share sX), one CTA/tile =====
// smem floats: sX [128][128] | Wt [128][68] | Wp [128][68] | Wg [64][68]
#define PJ_WT 16384
#define PJ_WP (16384 + 128*68)
#define PJ_WG (16384 + 2*128*68)
#define PJ_SMEM ((16384 + 2*128*68 + 64*68) * 4)

__global__ void __launch_bounds__(256) proj_kernel(
    const float* __restrict__ Hp, const float* __restrict__ Lp,
    const float* __restrict__ tw, const float* __restrict__ tb,
    const float* __restrict__ pw, const float* __restrict__ pb,
    const float* __restrict__ gw, const float* __restrict__ gb)
{
    extern __shared__ float sm[];
    float* sX = sm;
    const int b = blockIdx.y, p0 = blockIdx.x << 7, tid = threadIdx.x;

    for (int i = tid; i < 128 * 128; i += 256) {
        int c = i >> 7, p = i & 127;
        const float* src = (c < 64) ? Hp : Lp;
        sX[i] = src[(((b << 6) + (c & 63)) << 12) + p0 + p];
    }
    for (int i = tid; i < 64 * 128; i += 256) {
        int oc = i >> 7, c = i & 127;
        sm[PJ_WT + c * 68 + oc] = tw[i];
        sm[PJ_WP + c * 68 + oc] = pw[i];
    }
    for (int i = tid; i < 64 * 64; i += 256) {
        int oc = i >> 6, c = i & 63;
        sm[PJ_WG + c * 68 + oc] = gw[i];
    }
    __syncthreads();

    const int to = tid >> 4, tp = tid & 15;
    u64 acc[3][4][4];
    #pragma unroll
    for (int p = 0; p < 3; p++)
        #pragma unroll
        for (int i = 0; i < 4; i++)
            #pragma unroll
            for (int j = 0; j < 4; j++) acc[p][i][j] = 0ULL;

    for (int c = 0; c < 128; c++) {
        u64 x2[4];
        #pragma unroll
        for (int j = 0; j < 4; j++) x2[j] = *(const u64*)&sX[(c << 7) + 2 * tp + (j << 5)];
        float4 wt = *(const float4*)&sm[PJ_WT + c * 68 + 4 * to];
        float4 wp = *(const float4*)&sm[PJ_WP + c * 68 + 4 * to];
        u64 wtv[4] = { pk2(wt.x, wt.x), pk2(wt.y, wt.y), pk2(wt.z, wt.z), pk2(wt.w, wt.w) };
        u64 wpv[4] = { pk2(wp.x, wp.x), pk2(wp.y, wp.y), pk2(wp.z, wp.z), pk2(wp.w, wp.w) };
        #pragma unroll
        for (int i = 0; i < 4; i++)
            #pragma unroll
            for (int j = 0; j < 4; j++) {
                fma2(acc[0][i][j], wtv[i], x2[j]);
                fma2(acc[1][i][j], wpv[i], x2[j]);
            }
        if (c >= 64) {
            float4 wg = *(const float4*)&sm[PJ_WG + (c - 64) * 68 + 4 * to];
            u64 wgv[4] = { pk2(wg.x, wg.x), pk2(wg.y, wg.y), pk2(wg.z, wg.z), pk2(wg.w, wg.w) };
            #pragma unroll
            for (int i = 0; i < 4; i++)
                #pragma unroll
                for (int j = 0; j < 4; j++) fma2(acc[2][i][j], wgv[i], x2[j]);
        }
    }

    unsigned short* tHi = (unsigned short*)sm;
    unsigned short* tLo = (unsigned short*)((char*)sm + 16384);
    #pragma unroll
    for (int p = 0; p < 3; p++) {
        const float* bias = (p == 0) ? tb : (p == 1) ? pb : gb;
        __syncthreads();
        #pragma unroll
        for (int i = 0; i < 4; i++) {
            int o = 4 * to + i; float bo = bias[o];
            #pragma unroll
            for (int j = 0; j < 4; j++) {
                int px = 2 * tp + (j << 5);
                float2 a = upk2(acc[p][i][j]);
                float vx = a.x + bo, vy = a.y + bo;
                if (p == 2) {
                    tHi[px * 64 + o]       = __half_as_ushort(__float2half_rn(vx));
                    tHi[(px + 1) * 64 + o] = __half_as_ushort(__float2half_rn(vy));
                } else {
                    __nv_bfloat16 hx = __float2bfloat16_rn(vx), hy = __float2bfloat16_rn(vy);
                    tHi[px * 64 + o]       = *(unsigned short*)&hx;
                    tHi[(px + 1) * 64 + o] = *(unsigned short*)&hy;
                    __nv_bfloat16 lx = __float2bfloat16_rn(vx - __bfloat162float(hx));
                    __nv_bfloat16 ly = __float2bfloat16_rn(vy - __bfloat162float(hy));
                    tLo[px * 64 + o]       = *(unsigned short*)&lx;
                    tLo[(px + 1) * 64 + o] = *(unsigned short*)&ly;
                }
            }
        }
        __syncthreads();
        const uint4* shh = (const uint4*)tHi;
        if (p == 2) {
            uint4* dh = (uint4*)(g_Vh + ((size_t)b * 4096 + p0) * 64);
            for (int u = tid; u < 1024; u += 256) dh[u] = shh[u];
        } else {
            __nv_bfloat16* dHi = (p == 0) ? g_Khi : g_Qhi;
            __nv_bfloat16* dLo = (p == 0) ? g_Klo : g_Qlo;
            uint4* dh = (uint4*)(dHi + ((size_t)b * 4096 + p0) * 64);
            uint4* dl = (uint4*)(dLo + ((size_t)b * 4096 + p0) * 64);
            const uint4* sll = (const uint4*)tLo;
            for (int u = tid; u < 1024; u += 256) { dh[u] = shh[u]; dl[u] = sll[u]; }
        }
    }
}

// ================= Kernel 2: HMMA flash attention (unchanged from R8) =============
#define ATTN_SMEM 132096

__global__ void __launch_bounds__(256, 1) attn_kernel()
{
    extern __shared__ char smem[];
    const int tid = threadIdx.x, w = tid >> 5, l = tid & 31;
    const int qw = w & 3, kw = w >> 2;
    const int b = blockIdx.y, m0 = blockIdx.x << 7;
    const u32 sb  = smem_u32(smem);
    const u32 sQh = sb, sQl = sb + 16384;
    const u32 sK0 = sb + 32768;
    const u32 sV0 = sb + 98304;

    for (int u = tid; u < 1024; u += 256) {
        int row = u >> 3, ch = u & 7;
        size_t gq = ((size_t)(b * 4096 + m0 + row)) * 64 + ch * 8;
        size_t gk = ((size_t)(b * 4096 + row)) * 64 + ch * 8;
        u32 d = SWZ(row, ch);
        cpa16(sQh + d, g_Qhi + gq);
        cpa16(sQl + d, g_Qlo + gq);
        cpa16(sK0 + d, g_Khi + gk);
        cpa16(sK0 + 16384 + d, g_Klo + gk);
        cpa16(sV0 + d, g_Vh + gk);
    }
    cpa_commit(); cpa_wait0(); __syncthreads();

    const int R = qw << 5;
    u32 qh[8][4], ql[8][4];
    #pragma unroll
    for (int m = 0; m < 2; m++) {
        int arow = R + m * 16 + (l & 15);
        #pragma unroll
        for (int kk = 0; kk < 4; kk++) {
            u32 a = SWZ(arow, kk * 2 + (l >> 4));
            ldsm4(qh[m * 4 + kk], sQh + a);
            ldsm4(ql[m * 4 + kk], sQl + a);
        }
    }

    float esum[2][2] = {{0.f, 0.f}, {0.f, 0.f}};
    float mx[2][2] = {{-1e30f, -1e30f}, {-1e30f, -1e30f}};
    float eacc[2][8][4];
    #pragma unroll
    for (int m = 0; m < 2; m++)
        #pragma unroll
        for (int j = 0; j < 8; j++)
            #pragma unroll
            for (int q = 0; q < 4; q++) eacc[m][j][q] = 0.f;

    const int krow  = (kw << 6) + (l & 7) + ((l & 16) ? 8 : 0);
    const int kcsel = (l >> 3) & 1;
    const int vrow  = (kw << 6) + (l & 7) + ((l & 8) ? 8 : 0);
    const int vcsel = (l >> 4) & 1;

    for (int kt = 0; kt < 32; kt++) {
        const u32 kb = sK0 + (u32)(kt & 1) * 32768;
        const u32 vb = sV0 + (u32)(kt & 1) * 16384;

        if (kt + 1 < 32) {
            int n1 = (kt + 1) << 7;
            u32 kd = sK0 + (u32)((kt + 1) & 1) * 32768;
            u32 vd = sV0 + (u32)((kt + 1) & 1) * 16384;
            for (int u = tid; u < 1024; u += 256) {
                int row = u >> 3, ch = u & 7;
                size_t g = ((size_t)(b * 4096 + n1 + row)) * 64 + ch * 8;
                u32 d = SWZ(row, ch);
                cpa16(kd + d, g_Khi + g);
                cpa16(kd + 16384 + d, g_Klo + g);
                cpa16(vd + d, g_Vh + g);
            }
            cpa_commit();
        }

        #pragma unroll
        for (int sbk = 0; sbk < 2; sbk++) {
            float s[2][4][4];
            #pragma unroll
            for (int m = 0; m < 2; m++)
                #pragma unroll
                for (int nt = 0; nt < 4; nt++)
                    #pragma unroll
                    for (int q = 0; q < 4; q++) s[m][nt][q] = 0.f;

            #pragma unroll
            for (int nt2 = 0; nt2 < 2; nt2++) {
                #pragma unroll
                for (int kk = 0; kk < 4; kk++) {
                    u32 kh[4], klo[4];
                    int rr = sbk * 32 + nt2 * 16 + krow;
                    int ch = kk * 2 + kcsel;
                    ldsm4(kh,  kb + SWZ(rr, ch));
                    ldsm4(klo, kb + 16384 + SWZ(rr, ch));
                    #pragma unroll
                    for (int m = 0; m < 2; m++) {
                        mma_bf16(s[m][nt2 * 2 + 0], qh[m * 4 + kk], kh[0], kh[1]);
                        mma_bf16(s[m][nt2 * 2 + 0], qh[m * 4 + kk], klo[0], klo[1]);
                        mma_bf16(s[m][nt2 * 2 + 0], ql[m * 4 + kk], kh[0], kh[1]);
                        mma_bf16(s[m][nt2 * 2 + 1], qh[m * 4 + kk], kh[2], kh[3]);
                        mma_bf16(s[m][nt2 * 2 + 1], qh[m * 4 + kk], klo[2], klo[3]);
                        mma_bf16(s[m][nt2 * 2 + 1], ql[m * 4 + kk], kh[2], kh[3]);
                    }
                }
            }

            u32 ph[2][2][4];
            #pragma unroll
            for (int m = 0; m < 2; m++) {
                float t0 = s[m][0][0], t1 = s[m][0][2];
                #pragma unroll
                for (int nt = 0; nt < 4; nt++) {
                    t0 = fmaxf(t0, fmaxf(s[m][nt][0], s[m][nt][1]));
                    t1 = fmaxf(t1, fmaxf(s[m][nt][2], s[m][nt][3]));
                }
                t0 = fmaxf(t0, __shfl_xor_sync(0xffffffffu, t0, 1));
                t0 = fmaxf(t0, __shfl_xor_sync(0xffffffffu, t0, 2));
                t1 = fmaxf(t1, __shfl_xor_sync(0xffffffffu, t1, 1));
                t1 = fmaxf(t1, __shfl_xor_sync(0xffffffffu, t1, 2));
                float mn0 = fmaxf(mx[m][0], t0), mn1 = fmaxf(mx[m][1], t1);
                float a0 = __expf(mx[m][0] - mn0), a1 = __expf(mx[m][1] - mn1);
                mx[m][0] = mn0; mx[m][1] = mn1;
                esum[m][0] *= a0; esum[m][1] *= a1;
                #pragma unroll
                for (int j = 0; j < 8; j++) {
                    eacc[m][j][0] *= a0; eacc[m][j][1] *= a0;
                    eacc[m][j][2] *= a1; eacc[m][j][3] *= a1;
                }
                #pragma unroll
                for (int nt = 0; nt < 4; nt++) {
                    float e0 = __expf(s[m][nt][0] - mn0);
                    float e1 = __expf(s[m][nt][1] - mn0);
                    float e2 = __expf(s[m][nt][2] - mn1);
                    float e3 = __expf(s[m][nt][3] - mn1);
                    esum[m][0] += e0 + e1; esum[m][1] += e2 + e3;
                    ph[m][nt >> 1][((nt & 1) << 1) + 0] = pack_f16(e0, e1);
                    ph[m][nt >> 1][((nt & 1) << 1) + 1] = pack_f16(e2, e3);
                }
            }

            #pragma unroll
            for (int t = 0; t < 2; t++) {
                #pragma unroll
                for (int cb = 0; cb < 4; cb++) {
                    u32 vh[4];
                    int rr = sbk * 32 + t * 16 + vrow;
                    int ch = cb * 2 + vcsel;
                    ldsm4t(vh, vb + SWZ(rr, ch));
                    #pragma unroll
                    for (int m = 0; m < 2; m++) {
                        mma_f16(eacc[m][cb * 2 + 0], ph[m][t], vh[0], vh[1]);
                        mma_f16(eacc[m][cb * 2 + 1], ph[m][t], vh[2], vh[3]);
                    }
                }
            }
        }

        cpa_wait0();
        __syncthreads();
    }

    #pragma unroll
    for (int m = 0; m < 2; m++)
        #pragma unroll
        for (int hh = 0; hh < 2; hh++) {
            #pragma unroll
            for (int off = 1; off < 4; off <<= 1)
                esum[m][hh] += __shfl_xor_sync(0xffffffffu, esum[m][hh], off);
        }

    const int gr = l >> 2, c0 = 2 * (l & 3);
    float* sPart = (float*)smem;
    float* sSum  = (float*)(smem + 131072);
    float* sMax  = (float*)(smem + 131584);
    if (kw == 1) {
        #pragma unroll
        for (int m = 0; m < 2; m++) {
            int r0 = R + m * 16 + gr, r1 = r0 + 8;
            #pragma unroll
            for (int j = 0; j < 8; j++) {
                float* p  = &sPart[r0 * 66 + j * 8 + c0];
                float* p2 = &sPart[r1 * 66 + j * 8 + c0];
                p[0]  = eacc[m][j][0]; p[1]  = eacc[m][j][1];
                p2[0] = eacc[m][j][2]; p2[1] = eacc[m][j][3];
            }
            if ((l & 3) == 0) {
                sSum[r0] = esum[m][0]; sSum[r1] = esum[m][1];
                sMax[r0] = mx[m][0];   sMax[r1] = mx[m][1];
            }
        }
    }
    __syncthreads();
    float* sE = (float*)(smem + 65536);
    if (kw == 0) {
        #pragma unroll
        for (int m = 0; m < 2; m++) {
            int r0 = R + m * 16 + gr, r1 = r0 + 8;
            float mb0 = sMax[r0], mb1 = sMax[r1];
            float M0 = fmaxf(mx[m][0], mb0), M1 = fmaxf(mx[m][1], mb1);
            float fa0 = __expf(mx[m][0] - M0), fb0 = __expf(mb0 - M0);
            float fa1 = __expf(mx[m][1] - M1), fb1 = __expf(mb1 - M1);
            float inv0 = 1.f / (esum[m][0] * fa0 + sSum[r0] * fb0);
            float inv1 = 1.f / (esum[m][1] * fa1 + sSum[r1] * fb1);
            #pragma unroll
            for (int j = 0; j < 8; j++) {
                float* p  = &sPart[r0 * 66 + j * 8 + c0];
                float* p2 = &sPart[r1 * 66 + j * 8 + c0];
                int c = 8 * j + c0;
                sE[c * 132 + r0]       = (eacc[m][j][0] * fa0 + p[0]  * fb0) * inv0;
                sE[(c + 1) * 132 + r0] = (eacc[m][j][1] * fa0 + p[1]  * fb0) * inv0;
                sE[c * 132 + r1]       = (eacc[m][j][2] * fa1 + p2[0] * fb1) * inv1;
                sE[(c + 1) * 132 + r1] = (eacc[m][j][3] * fa1 + p2[1] * fb1) * inv1;
            }
        }
    }
    __syncthreads();
    for (int u = tid; u < 2048; u += 256) {
        int c = u >> 5, q = u & 31;
        float4 v = *(float4*)&sE[c * 132 + q * 4];
        *(float4*)&g_E[(((b << 6) + c) << 12) + m0 + q * 4] = v;
    }
}

// ============ Kernel 3: conv3x3 + BN + ReLU + residual (FFMA2, oc-split x4) ========
__global__ void __launch_bounds__(128) conv_kernel(
    const float* __restrict__ Hp,
    const float* __restrict__ cw, const float* __restrict__ cb,
    const float* __restrict__ gamma, const float* __restrict__ beta,
    const float* __restrict__ mean, const float* __restrict__ var,
    float* __restrict__ out)
{
    extern __shared__ float sW[];  // [ic*9+kk][16]
    const int tid = threadIdx.x, b = blockIdx.y, y0 = blockIdx.x << 1;
    const int oh = blockIdx.z << 4;
    for (int i = tid; i < 64 * 9 * 16; i += 128) {
        int ocl = i / 576, rem = i - ocl * 576;
        sW[rem * 16 + ocl] = cw[(oh + ocl) * 576 + rem];
    }
    __syncthreads();
    const int y = y0 + (tid >> 6), x = tid & 63;
    u64 acc2[8];
    #pragma unroll
    for (int i = 0; i < 8; i++) acc2[i] = 0ULL;
    for (int ic = 0; ic < 64; ic++) {
        const float* src = &g_E[(((b << 6) + ic) << 12)];
        float in9[9];
        #pragma unroll
        for (int dy = 0; dy < 3; dy++) {
            int yy = y + dy - 1; bool yok = (yy >= 0) && (yy < 64);
            #pragma unroll
            for (int dx = 0; dx < 3; dx++) {
                int xx = x + dx - 1;
                in9[dy * 3 + dx] = (yok && xx >= 0 && xx < 64) ? src[(yy << 6) + xx] : 0.f;
            }
        }
        #pragma unroll
        for (int kk = 0; kk < 9; kk++) {
            u64 iv = pk2(in9[kk], in9[kk]);
            const u64* wr = (const u64*)&sW[(ic * 9 + kk) << 4];
            #pragma unroll
            for (int q = 0; q < 8; q++) fma2(acc2[q], iv, wr[q]);
        }
    }
    const int pix = (y << 6) + x;
    #pragma unroll
    for (int q = 0; q < 8; q++) {
        float2 a = upk2(acc2[q]);
        #pragma unroll
        for (int h = 0; h < 2; h++) {
            int oc = oh + 2 * q + h;
            float v = (h ? a.y : a.x) + cb[oc];
            v = (v - mean[oc]) * (gamma[oc] * rsqrtf(var[oc] + 1e-5f)) + beta[oc];
            v = fmaxf(v, 0.f);
            int idx = (((b << 6) + oc) << 12) + pix;
            out[idx] = Hp[idx] + v;
        }
    }
}

extern "C" void kernel_launch(void* const* d_in, const int* in_sizes, int n_in,
                              void* d_out, int out_size)
{
    const float* Hp = (const float*)d_in[0];
    const float* Lp = (const float*)d_in[1];
    const float* tw = (const float*)d_in[2];  const float* tb = (const float*)d_in[3];
    const float* pw = (const float*)d_in[4];  const float* pb = (const float*)d_in[5];
    const float* gw = (const float*)d_in[6];  const float* gb = (const float*)d_in[7];
    const float* cw = (const float*)d_in[8];  const float* cb = (const float*)d_in[9];
    const float* gamma = (const float*)d_in[10]; const float* beta = (const float*)d_in[11];
    const float* mean = (const float*)d_in[12];  const float* var = (const float*)d_in[13];
    float* out = (float*)d_out;

    const int smem_conv = 64 * 9 * 16 * 4;
    cudaFuncSetAttribute(proj_kernel, cudaFuncAttributeMaxDynamicSharedMemorySize, PJ_SMEM);
    cudaFuncSetAttribute(attn_kernel, cudaFuncAttributeMaxDynamicSharedMemorySize, ATTN_SMEM);
    cudaFuncSetAttribute(conv_kernel, cudaFuncAttributeMaxDynamicSharedMemorySize, smem_conv);

    proj_kernel<<<dim3(32, 4), 256, PJ_SMEM>>>(Hp, Lp, tw, tb, pw, pb, gw, gb);
    attn_kernel<<<dim3(32, 4), 256, ATTN_SMEM>>>();
    conv_kernel<<<dim3(32, 4, 4), 128, smem_conv>>>(Hp, cw, cb, gamma, beta, mean, var, out);
}

// round 11
// speedup vs baseline: 1.4535x; 1.4535x over previous
#include <cuda_runtime.h>
#include <cuda_bf16.h>
#include <cuda_fp16.h>
typedef unsigned int u32; typedef unsigned long long u64;

#define NELEM (4*4096*64)
__device__ __nv_bfloat16 g_Khi[NELEM], g_Klo[NELEM];   // [b][n][c]
__device__ __nv_bfloat16 g_Qhi[NELEM], g_Qlo[NELEM];   // [b][m][c]
__device__ __half        g_Vh [NELEM];                  // [b][n][c]  fp16
__device__ float g_E[NELEM];                            // [b][c][n]

#define SWZ(row, chunk) (((u32)(row) << 7) + ((u32)(((chunk) ^ ((row) & 7))) << 4))

__device__ __forceinline__ u32 smem_u32(const void* p) {
    u32 a; asm("{ .reg .u64 t; cvta.to.shared.u64 t, %1; cvt.u32.u64 %0, t; }" : "=r"(a) : "l"(p)); return a;
}
__device__ __forceinline__ void cpa16(u32 dst, const void* src) {
    asm volatile("cp.async.cg.shared.global [%0], [%1], 16;" :: "r"(dst), "l"(src));
}
__device__ __forceinline__ void cpa_commit() { asm volatile("cp.async.commit_group;"); }
__device__ __forceinline__ void cpa_wait0()  { asm volatile("cp.async.wait_group 0;"); }
__device__ __forceinline__ void ldsm4(u32* r, u32 a) {
    asm volatile("ldmatrix.sync.aligned.m8n8.x4.shared.b16 {%0,%1,%2,%3},[%4];"
        : "=r"(r[0]), "=r"(r[1]), "=r"(r[2]), "=r"(r[3]) : "r"(a));
}
__device__ __forceinline__ void ldsm4t(u32* r, u32 a) {
    asm volatile("ldmatrix.sync.aligned.m8n8.x4.trans.shared.b16 {%0,%1,%2,%3},[%4];"
        : "=r"(r[0]), "=r"(r[1]), "=r"(r[2]), "=r"(r[3]) : "r"(a));
}
__device__ __forceinline__ void mma_bf16(float* d, const u32* a, u32 b0, u32 b1) {
    asm volatile("mma.sync.aligned.m16n8k16.row.col.f32.bf16.bf16.f32 "
        "{%0,%1,%2,%3},{%4,%5,%6,%7},{%8,%9},{%0,%1,%2,%3};"
        : "+f"(d[0]), "+f"(d[1]), "+f"(d[2]), "+f"(d[3])
        : "r"(a[0]), "r"(a[1]), "r"(a[2]), "r"(a[3]), "r"(b0), "r"(b1));
}
__device__ __forceinline__ void mma_f16(float* d, const u32* a, u32 b0, u32 b1) {
    asm volatile("mma.sync.aligned.m16n8k16.row.col.f32.f16.f16.f32 "
        "{%0,%1,%2,%3},{%4,%5,%6,%7},{%8,%9},{%0,%1,%2,%3};"
        : "+f"(d[0]), "+f"(d[1]), "+f"(d[2]), "+f"(d[3])
        : "r"(a[0]), "r"(a[1]), "r"(a[2]), "r"(a[3]), "r"(b0), "r"(b1));
}
__device__ __forceinline__ u32 pack_f16(float lo, float hi) {
    __half2 h = __floats2half2_rn(lo, hi);
    return *(u32*)&h;
}
__device__ __forceinline__ u64 pk2(float x, float y) {
    u64 r; asm("mov.b64 %0, {%1,%2};" : "=l"(r) : "f"(x), "f"(y)); return r;
}
__device__ __forceinline__ float2 upk2(u64 v) {
    float2 f; asm("mov.b64 {%0,%1}, %2;" : "=f"(f.x), "=f"(f.y) : "l"(v)); return f;
}
__device__ __forceinline__ void fma2(u64 &d, u64 a, u64 b) {
    asm("fma.rn.f32x2 %0, %1, %2, %0;" : "+l"(d) : "l"(a), "l"(b));
}

// ========== Kernel 1: projections, 64-px tiles (3 CTAs/SM), 72-padded epilogue ====
// smem floats: sX [IC][64] (8192 fl) | sWT [IC][68] at float 8192
#define PJ_WT 8192
#define PJ_SMEM ((8192 + 128*68) * 4)    // 67584 B

__global__ void __launch_bounds__(256) proj_kernel(
    const float* __restrict__ Hp, const float* __restrict__ Lp,
    const float* __restrict__ tw, const float* __restrict__ tb,
    const float* __restrict__ pw, const float* __restrict__ pb,
    const float* __restrict__ gw, const float* __restrict__ gb)
{
    extern __shared__ float sm[];
    float* sX = sm;
    const int proj = blockIdx.y, b = blockIdx.z, p0 = blockIdx.x << 6, tid = threadIdx.x;
    const float* W; const float* bias; int IC;
    if (proj == 0)      { W = tw; bias = tb; IC = 128; }
    else if (proj == 1) { W = pw; bias = pb; IC = 128; }
    else                { W = gw; bias = gb; IC = 64;  }

    for (int i = tid; i < IC * 64; i += 256) {
        int c = i >> 6, p = i & 63;
        const float* src = (proj == 2) ? Lp : ((c < 64) ? Hp : Lp);
        sX[i] = src[(((b << 6) + (c & 63)) << 12) + p0 + p];
    }
    for (int i = tid; i < 64 * IC; i += 256) {
        int oc = i / IC, c = i - oc * IC;
        sm[PJ_WT + c * 68 + oc] = W[i];
    }
    __syncthreads();

    const int to = tid >> 4, tp = tid & 15;
    u64 acc[4][2];
    #pragma unroll
    for (int i = 0; i < 4; i++) { acc[i][0] = 0ULL; acc[i][1] = 0ULL; }
    #pragma unroll 2
    for (int c = 0; c < IC; c++) {
        float4 w4 = *(const float4*)&sm[PJ_WT + c * 68 + 4 * to];
        u64 wv[4] = { pk2(w4.x, w4.x), pk2(w4.y, w4.y), pk2(w4.z, w4.z), pk2(w4.w, w4.w) };
        u64 x0 = *(const u64*)&sX[(c << 6) + 2 * tp];
        u64 x1 = *(const u64*)&sX[(c << 6) + 2 * tp + 32];
        #pragma unroll
        for (int i = 0; i < 4; i++) { fma2(acc[i][0], wv[i], x0); fma2(acc[i][1], wv[i], x1); }
    }
    __syncthreads();
    // stage [px][72-padded c] halves (72 ushorts = 144 B -> 16B-aligned rows)
    unsigned short* tHi = (unsigned short*)sm;                       // [64][72] = 9216 B
    unsigned short* tLo = (unsigned short*)((char*)sm + 9216);       // [64][72]
    #pragma unroll
    for (int i = 0; i < 4; i++) {
        int o = 4 * to + i; float bo = bias[o];
        #pragma unroll
        for (int j = 0; j < 2; j++) {
            int px = 2 * tp + (j << 5);
            float2 a = upk2(acc[i][j]);
            float vx = a.x + bo, vy = a.y + bo;
            if (proj == 2) {
                tHi[px * 72 + o]       = __half_as_ushort(__float2half_rn(vx));
                tHi[(px + 1) * 72 + o] = __half_as_ushort(__float2half_rn(vy));
            } else {
                __nv_bfloat16 hx = __float2bfloat16_rn(vx), hy = __float2bfloat16_rn(vy);
                tHi[px * 72 + o]       = *(unsigned short*)&hx;
                tHi[(px + 1) * 72 + o] = *(unsigned short*)&hy;
                __nv_bfloat16 lx = __float2bfloat16_rn(vx - __bfloat162float(hx));
                __nv_bfloat16 ly = __float2bfloat16_rn(vy - __bfloat162float(hy));
                tLo[px * 72 + o]       = *(unsigned short*)&lx;
                tLo[(px + 1) * 72 + o] = *(unsigned short*)&ly;
            }
        }
    }
    __syncthreads();
    // copy out 64 rows x 64 c: 512 uint4 chunks (8 ushorts each)
    if (proj == 2) {
        uint4* dh = (uint4*)(g_Vh + ((size_t)b * 4096 + p0) * 64);
        for (int u = tid; u < 512; u += 256) {
            int row = u >> 3, cc = u & 7;
            dh[u] = *(const uint4*)&tHi[row * 72 + cc * 8];
        }
    } else {
        __nv_bfloat16* dHi = (proj == 0) ? g_Khi : g_Qhi;
        __nv_bfloat16* dLo = (proj == 0) ? g_Klo : g_Qlo;
        uint4* dh = (uint4*)(dHi + ((size_t)b * 4096 + p0) * 64);
        uint4* dl = (uint4*)(dLo + ((size_t)b * 4096 + p0) * 64);
        for (int u = tid; u < 512; u += 256) {
            int row = u >> 3, cc = u & 7;
            dh[u] = *(const uint4*)&tHi[row * 72 + cc * 8];
            dl[u] = *(const uint4*)&tLo[row * 72 + cc * 8];
        }
    }
}

// ================= Kernel 2: HMMA flash attention (R8, unchanged) =================
#define ATTN_SMEM 132096

__global__ void __launch_bounds__(256, 1) attn_kernel()
{
    extern __shared__ char smem[];
    const int tid = threadIdx.x, w = tid >> 5, l = tid & 31;
    const int qw = w & 3, kw = w >> 2;
    const int b = blockIdx.y, m0 = blockIdx.x << 7;
    const u32 sb  = smem_u32(smem);
    const u32 sQh = sb, sQl = sb + 16384;
    const u32 sK0 = sb + 32768;
    const u32 sV0 = sb + 98304;

    for (int u = tid; u < 1024; u += 256) {
        int row = u >> 3, ch = u & 7;
        size_t gq = ((size_t)(b * 4096 + m0 + row)) * 64 + ch * 8;
        size_t gk = ((size_t)(b * 4096 + row)) * 64 + ch * 8;
        u32 d = SWZ(row, ch);
        cpa16(sQh + d, g_Qhi + gq);
        cpa16(sQl + d, g_Qlo + gq);
        cpa16(sK0 + d, g_Khi + gk);
        cpa16(sK0 + 16384 + d, g_Klo + gk);
        cpa16(sV0 + d, g_Vh + gk);
    }
    cpa_commit(); cpa_wait0(); __syncthreads();

    const int R = qw << 5;
    u32 qh[8][4], ql[8][4];
    #pragma unroll
    for (int m = 0; m < 2; m++) {
        int arow = R + m * 16 + (l & 15);
        #pragma unroll
        for (int kk = 0; kk < 4; kk++) {
            u32 a = SWZ(arow, kk * 2 + (l >> 4));
            ldsm4(qh[m * 4 + kk], sQh + a);
            ldsm4(ql[m * 4 + kk], sQl + a);
        }
    }

    float esum[2][2] = {{0.f, 0.f}, {0.f, 0.f}};
    float mx[2][2] = {{-1e30f, -1e30f}, {-1e30f, -1e30f}};
    float eacc[2][8][4];
    #pragma unroll
    for (int m = 0; m < 2; m++)
        #pragma unroll
        for (int j = 0; j < 8; j++)
            #pragma unroll
            for (int q = 0; q < 4; q++) eacc[m][j][q] = 0.f;

    const int krow  = (kw << 6) + (l & 7) + ((l & 16) ? 8 : 0);
    const int kcsel = (l >> 3) & 1;
    const int vrow  = (kw << 6) + (l & 7) + ((l & 8) ? 8 : 0);
    const int vcsel = (l >> 4) & 1;

    for (int kt = 0; kt < 32; kt++) {
        const u32 kb = sK0 + (u32)(kt & 1) * 32768;
        const u32 vb = sV0 + (u32)(kt & 1) * 16384;

        if (kt + 1 < 32) {
            int n1 = (kt + 1) << 7;
            u32 kd = sK0 + (u32)((kt + 1) & 1) * 32768;
            u32 vd = sV0 + (u32)((kt + 1) & 1) * 16384;
            for (int u = tid; u < 1024; u += 256) {
                int row = u >> 3, ch = u & 7;
                size_t g = ((size_t)(b * 4096 + n1 + row)) * 64 + ch * 8;
                u32 d = SWZ(row, ch);
                cpa16(kd + d, g_Khi + g);
                cpa16(kd + 16384 + d, g_Klo + g);
                cpa16(vd + d, g_Vh + g);
            }
            cpa_commit();
        }

        #pragma unroll
        for (int sbk = 0; sbk < 2; sbk++) {
            float s[2][4][4];
            #pragma unroll
            for (int m = 0; m < 2; m++)
                #pragma unroll
                for (int nt = 0; nt < 4; nt++)
                    #pragma unroll
                    for (int q = 0; q < 4; q++) s[m][nt][q] = 0.f;

            #pragma unroll
            for (int nt2 = 0; nt2 < 2; nt2++) {
                #pragma unroll
                for (int kk = 0; kk < 4; kk++) {
                    u32 kh[4], klo[4];
                    int rr = sbk * 32 + nt2 * 16 + krow;
                    int ch = kk * 2 + kcsel;
                    ldsm4(kh,  kb + SWZ(rr, ch));
                    ldsm4(klo, kb + 16384 + SWZ(rr, ch));
                    #pragma unroll
                    for (int m = 0; m < 2; m++) {
                        mma_bf16(s[m][nt2 * 2 + 0], qh[m * 4 + kk], kh[0], kh[1]);
                        mma_bf16(s[m][nt2 * 2 + 0], qh[m * 4 + kk], klo[0], klo[1]);
                        mma_bf16(s[m][nt2 * 2 + 0], ql[m * 4 + kk], kh[0], kh[1]);
                        mma_bf16(s[m][nt2 * 2 + 1], qh[m * 4 + kk], kh[2], kh[3]);
                        mma_bf16(s[m][nt2 * 2 + 1], qh[m * 4 + kk], klo[2], klo[3]);
                        mma_bf16(s[m][nt2 * 2 + 1], ql[m * 4 + kk], kh[2], kh[3]);
                    }
                }
            }

            u32 ph[2][2][4];
            #pragma unroll
            for (int m = 0; m < 2; m++) {
                float t0 = s[m][0][0], t1 = s[m][0][2];
                #pragma unroll
                for (int nt = 0; nt < 4; nt++) {
                    t0 = fmaxf(t0, fmaxf(s[m][nt][0], s[m][nt][1]));
                    t1 = fmaxf(t1, fmaxf(s[m][nt][2], s[m][nt][3]));
                }
                t0 = fmaxf(t0, __shfl_xor_sync(0xffffffffu, t0, 1));
                t0 = fmaxf(t0, __shfl_xor_sync(0xffffffffu, t0, 2));
                t1 = fmaxf(t1, __shfl_xor_sync(0xffffffffu, t1, 1));
                t1 = fmaxf(t1, __shfl_xor_sync(0xffffffffu, t1, 2));
                float mn0 = fmaxf(mx[m][0], t0), mn1 = fmaxf(mx[m][1], t1);
                float a0 = __expf(mx[m][0] - mn0), a1 = __expf(mx[m][1] - mn1);
                mx[m][0] = mn0; mx[m][1] = mn1;
                esum[m][0] *= a0; esum[m][1] *= a1;
                #pragma unroll
                for (int j = 0; j < 8; j++) {
                    eacc[m][j][0] *= a0; eacc[m][j][1] *= a0;
                    eacc[m][j][2] *= a1; eacc[m][j][3] *= a1;
                }
                #pragma unroll
                for (int nt = 0; nt < 4; nt++) {
                    float e0 = __expf(s[m][nt][0] - mn0);
                    float e1 = __expf(s[m][nt][1] - mn0);
                    float e2 = __expf(s[m][nt][2] - mn1);
                    float e3 = __expf(s[m][nt][3] - mn1);
                    esum[m][0] += e0 + e1; esum[m][1] += e2 + e3;
                    ph[m][nt >> 1][((nt & 1) << 1) + 0] = pack_f16(e0, e1);
                    ph[m][nt >> 1][((nt & 1) << 1) + 1] = pack_f16(e2, e3);
                }
            }

            #pragma unroll
            for (int t = 0; t < 2; t++) {
                #pragma unroll
                for (int cb = 0; cb < 4; cb++) {
                    u32 vh[4];
                    int rr = sbk * 32 + t * 16 + vrow;
                    int ch = cb * 2 + vcsel;
                    ldsm4t(vh, vb + SWZ(rr, ch));
                    #pragma unroll
                    for (int m = 0; m < 2; m++) {
                        mma_f16(eacc[m][cb * 2 + 0], ph[m][t], vh[0], vh[1]);
                        mma_f16(eacc[m][cb * 2 + 1], ph[m][t], vh[2], vh[3]);
                    }
                }
            }
        }

        cpa_wait0();
        __syncthreads();
    }

    #pragma unroll
    for (int m = 0; m < 2; m++)
        #pragma unroll
        for (int hh = 0; hh < 2; hh++) {
            #pragma unroll
            for (int off = 1; off < 4; off <<= 1)
                esum[m][hh] += __shfl_xor_sync(0xffffffffu, esum[m][hh], off);
        }

    const int gr = l >> 2, c0 = 2 * (l & 3);
    float* sPart = (float*)smem;
    float* sSum  = (float*)(smem + 131072);
    float* sMax  = (float*)(smem + 131584);
    if (kw == 1) {
        #pragma unroll
        for (int m = 0; m < 2; m++) {
            int r0 = R + m * 16 + gr, r1 = r0 + 8;
            #pragma unroll
            for (int j = 0; j < 8; j++) {
                float* p  = &sPart[r0 * 66 + j * 8 + c0];
                float* p2 = &sPart[r1 * 66 + j * 8 + c0];
                p[0]  = eacc[m][j][0]; p[1]  = eacc[m][j][1];
                p2[0] = eacc[m][j][2]; p2[1] = eacc[m][j][3];
            }
            if ((l & 3) == 0) {
                sSum[r0] = esum[m][0]; sSum[r1] = esum[m][1];
                sMax[r0] = mx[m][0];   sMax[r1] = mx[m][1];
            }
        }
    }
    __syncthreads();
    float* sE = (float*)(smem + 65536);
    if (kw == 0) {
        #pragma unroll
        for (int m = 0; m < 2; m++) {
            int r0 = R + m * 16 + gr, r1 = r0 + 8;
            float mb0 = sMax[r0], mb1 = sMax[r1];
            float M0 = fmaxf(mx[m][0], mb0), M1 = fmaxf(mx[m][1], mb1);
            float fa0 = __expf(mx[m][0] - M0), fb0 = __expf(mb0 - M0);
            float fa1 = __expf(mx[m][1] - M1), fb1 = __expf(mb1 - M1);
            float inv0 = 1.f / (esum[m][0] * fa0 + sSum[r0] * fb0);
            float inv1 = 1.f / (esum[m][1] * fa1 + sSum[r1] * fb1);
            #pragma unroll
            for (int j = 0; j < 8; j++) {
                float* p  = &sPart[r0 * 66 + j * 8 + c0];
                float* p2 = &sPart[r1 * 66 + j * 8 + c0];
                int c = 8 * j + c0;
                sE[c * 132 + r0]       = (eacc[m][j][0] * fa0 + p[0]  * fb0) * inv0;
                sE[(c + 1) * 132 + r0] = (eacc[m][j][1] * fa0 + p[1]  * fb0) * inv0;
                sE[c * 132 + r1]       = (eacc[m][j][2] * fa1 + p2[0] * fb1) * inv1;
                sE[(c + 1) * 132 + r1] = (eacc[m][j][3] * fa1 + p2[1] * fb1) * inv1;
            }
        }
    }
    __syncthreads();
    for (int u = tid; u < 2048; u += 256) {
        int c = u >> 5, q = u & 31;
        float4 v = *(float4*)&sE[c * 132 + q * 4];
        *(float4*)&g_E[(((b << 6) + c) << 12) + m0 + q * 4] = v;
    }
}

// ============ Kernel 3: conv3x3 + BN + ReLU + residual (R8: FFMA2, oc-split x2) ====
__global__ void __launch_bounds__(128) conv_kernel(
    const float* __restrict__ Hp,
    const float* __restrict__ cw, const float* __restrict__ cb,
    const float* __restrict__ gamma, const float* __restrict__ beta,
    const float* __restrict__ mean, const float* __restrict__ var,
    float* __restrict__ out)
{
    extern __shared__ float sW[];  // [ic*9+kk][32]
    const int tid = threadIdx.x, b = blockIdx.y, y0 = blockIdx.x << 1;
    const int oh = blockIdx.z << 5;
    for (int i = tid; i < 64 * 9 * 32; i += 128) {
        int ocl = i / 576, rem = i - ocl * 576;
        sW[rem * 32 + ocl] = cw[(oh + ocl) * 576 + rem];
    }
    __syncthreads();
    const int y = y0 + (tid >> 6), x = tid & 63;
    u64 acc2[16];
    #pragma unroll
    for (int i = 0; i < 16; i++) acc2[i] = 0ULL;
    for (int ic = 0; ic < 64; ic++) {
        const float* src = &g_E[(((b << 6) + ic) << 12)];
        float in9[9];
        #pragma unroll
        for (int dy = 0; dy < 3; dy++) {
            int yy = y + dy - 1; bool yok = (yy >= 0) && (yy < 64);
            #pragma unroll
            for (int dx = 0; dx < 3; dx++) {
                int xx = x + dx - 1;
                in9[dy * 3 + dx] = (yok && xx >= 0 && xx < 64) ? src[(yy << 6) + xx] : 0.f;
            }
        }
        #pragma unroll
        for (int kk = 0; kk < 9; kk++) {
            u64 iv = pk2(in9[kk], in9[kk]);
            const u64* wr = (const u64*)&sW[(ic * 9 + kk) << 5];
            #pragma unroll
            for (int q = 0; q < 16; q++) fma2(acc2[q], iv, wr[q]);
        }
    }
    const int pix = (y << 6) + x;
    #pragma unroll
    for (int q = 0; q < 16; q++) {
        float2 a = upk2(acc2[q]);
        #pragma unroll
        for (int h = 0; h < 2; h++) {
            int oc = oh + 2 * q + h;
            float v = (h ? a.y : a.x) + cb[oc];
            v = (v - mean[oc]) * (gamma[oc] * rsqrtf(var[oc] + 1e-5f)) + beta[oc];
            v = fmaxf(v, 0.f);
            int idx = (((b << 6) + oc) << 12) + pix;
            out[idx] = Hp[idx] + v;
        }
    }
}

extern "C" void kernel_launch(void* const* d_in, const int* in_sizes, int n_in,
                              void* d_out, int out_size)
{
    const float* Hp = (const float*)d_in[0];
    const float* Lp = (const float*)d_in[1];
    const float* tw = (const float*)d_in[2];  const float* tb = (const float*)d_in[3];
    const float* pw = (const float*)d_in[4];  const float* pb = (const float*)d_in[5];
    const float* gw = (const float*)d_in[6];  const float* gb = (const float*)d_in[7];
    const float* cw = (const float*)d_in[8];  const float* cb = (const float*)d_in[9];
    const float* gamma = (const float*)d_in[10]; const float* beta = (const float*)d_in[11];
    const float* mean = (const float*)d_in[12];  const float* var = (const float*)d_in[13];
    float* out = (float*)d_out;

    const int smem_conv = 64 * 9 * 32 * 4;
    cudaFuncSetAttribute(proj_kernel, cudaFuncAttributeMaxDynamicSharedMemorySize, PJ_SMEM);
    cudaFuncSetAttribute(attn_kernel, cudaFuncAttributeMaxDynamicSharedMemorySize, ATTN_SMEM);
    cudaFuncSetAttribute(conv_kernel, cudaFuncAttributeMaxDynamicSharedMemorySize, smem_conv);

    proj_kernel<<<dim3(64, 3, 4), 256, PJ_SMEM>>>(Hp, Lp, tw, tb, pw, pb, gw, gb);
    attn_kernel<<<dim3(32, 4), 256, ATTN_SMEM>>>();
    conv_kernel<<<dim3(32, 4, 2), 128, smem_conv>>>(Hp, cw, cb, gamma, beta, mean, var, out);
}